// round 1
// baseline (speedup 1.0000x reference)
#include <cuda_runtime.h>
#include <cuda_bf16.h>
#include <cstdint>

// ---------------------------------------------------------------------------
// Scratch (static __device__ arrays; no allocation allowed)
// ---------------------------------------------------------------------------
__device__ float g_bufA[32u * 768u * 1024u];   // ~100 MB ping
__device__ float g_bufB[32u * 768u * 1024u];   // ~100 MB pong
__device__ float g_wt[4u * 768u * 768u];       // transposed weights [tap][ci][co]
__device__ float g_w6t[768u * 64u];            // w6 transposed [ci][d]
__device__ float g_z[32u * 511u * 64u];        // encoder output, [B][T'][D]
__device__ float g_enorm[512];
__device__ float g_counts[512];
__device__ float g_loss[1];

// ---------------------------------------------------------------------------
// f32x2 helpers (packed dual-FP32 FMA — 2x fp32 throughput on sm_103a)
// ---------------------------------------------------------------------------
__device__ __forceinline__ void fma2(unsigned long long& d,
                                     unsigned long long a,
                                     unsigned long long b) {
    asm("fma.rn.f32x2 %0, %1, %2, %0;" : "+l"(d) : "l"(a), "l"(b));
}
__device__ __forceinline__ float2 unpack2(unsigned long long v) {
    float2 r;
    asm("mov.b64 {%0, %1}, %2;" : "=f"(r.x), "=f"(r.y) : "l"(v));
    return r;
}

// ---------------------------------------------------------------------------
// Weight transpose: w[CO][CI][KS] -> wt[tap][ci][co]  (coalesced writes)
// ---------------------------------------------------------------------------
__global__ void transpose_w_kernel(const float* __restrict__ w,
                                   float* __restrict__ wt, int CI, int KS) {
    int total = 768 * CI * KS;
    int idx = blockIdx.x * 256 + threadIdx.x;
    if (idx >= total) return;
    int co = idx % 768;
    int r = idx / 768;
    int ci = r % CI;
    int tap = r / CI;
    wt[idx] = w[((size_t)co * CI + ci) * KS + tap];
}

__global__ void transpose_w6_kernel(const float* __restrict__ w6,
                                    float* __restrict__ w6t) {
    int idx = blockIdx.x * 256 + threadIdx.x;
    if (idx >= 768 * 64) return;
    int d = idx & 63;
    int ci = idx >> 6;
    w6t[idx] = w6[(size_t)d * 768 + ci];
}

// ---------------------------------------------------------------------------
// Conv1d + folded BN + ReLU, implicit GEMM.
// Tile: 128 co x 128 t per block, 256 threads, 8x8 outputs/thread as
// 4 co-pairs x 8 t in packed f32x2 accumulators.
// x:   [B][CIN][TS_in] (logical T_in), wt: [tap][ci][768]
// out: [B][768][TS_out] (logical T_out)
// ---------------------------------------------------------------------------
template <int CIN, int KS, int STRIDE, int PAD>
__global__ void __launch_bounds__(256, 2)
conv_bn_relu_kernel(const float* __restrict__ x, const float* __restrict__ wt,
                    const float* __restrict__ gamma, const float* __restrict__ beta,
                    const float* __restrict__ mean, const float* __restrict__ var,
                    float* __restrict__ out,
                    int T_in, int TS_in, int T_out, int TS_out) {
    constexpr int SPAN = 127 * STRIDE + KS;  // input span covering 128 outputs
    __shared__ float sA[8][KS * 128];        // weights: [ci_kk][tap*128 + co]
    __shared__ float2 sB[8][SPAN];           // inputs, duplicated (v,v)

    const int b = blockIdx.z;
    const int co0 = blockIdx.y * 128;
    const int t0 = blockIdx.x * 128;
    const int tid = threadIdx.x;
    const int warp = tid >> 5;
    const int lane = tid & 31;
    const int tm = tid >> 4;   // 0..15 -> co group of 8
    const int tn = tid & 15;   // 0..15 -> t  group of 8

    unsigned long long acc[4][8];
#pragma unroll
    for (int i = 0; i < 4; ++i)
#pragma unroll
        for (int j = 0; j < 8; ++j) acc[i][j] = 0ull;

    const float* xb = x + (size_t)b * CIN * TS_in;
    const int tin_start = t0 * STRIDE - PAD;

    for (int ci0 = 0; ci0 < CIN; ci0 += 8) {
        __syncthreads();
        {
            const int ci = ci0 + warp;
#pragma unroll
            for (int tap = 0; tap < KS; ++tap) {
                float4 v = *(const float4*)(wt + ((size_t)(tap * CIN + ci)) * 768 +
                                            co0 + lane * 4);
                *(float4*)&sA[warp][tap * 128 + lane * 4] = v;
            }
            const float* xr = xb + (size_t)ci * TS_in;
            for (int p = lane; p < SPAN; p += 32) {
                int tin = tin_start + p;
                float v = (tin >= 0 && tin < T_in) ? xr[tin] : 0.0f;
                sB[warp][p] = make_float2(v, v);
            }
        }
        __syncthreads();

#pragma unroll
        for (int kk = 0; kk < 8; ++kk) {
#pragma unroll
            for (int tap = 0; tap < KS; ++tap) {
                ulonglong2 A0 = *(const ulonglong2*)&sA[kk][tap * 128 + tm * 8];
                ulonglong2 A1 = *(const ulonglong2*)&sA[kk][tap * 128 + tm * 8 + 4];
                const unsigned long long ap0 = A0.x, ap1 = A0.y, ap2 = A1.x, ap3 = A1.y;
                const int base = tn * 8 * STRIDE + tap;
#pragma unroll
                for (int j = 0; j < 8; ++j) {
                    unsigned long long bv =
                        *(const unsigned long long*)&sB[kk][base + j * STRIDE];
                    fma2(acc[0][j], ap0, bv);
                    fma2(acc[1][j], ap1, bv);
                    fma2(acc[2][j], ap2, bv);
                    fma2(acc[3][j], ap3, bv);
                }
            }
        }
    }

    // Epilogue: folded BN + ReLU, vectorized stores (TS_out keeps 16B alignment)
    const int tbase = t0 + tn * 8;
#pragma unroll
    for (int i = 0; i < 4; ++i) {
        const int ce = co0 + tm * 8 + 2 * i;
        const float ae = gamma[ce] / sqrtf(var[ce] + 1e-5f);
        const float be = beta[ce] - mean[ce] * ae;
        const float ao = gamma[ce + 1] / sqrtf(var[ce + 1] + 1e-5f);
        const float bo = beta[ce + 1] - mean[ce + 1] * ao;
        float ve[8], vo[8];
#pragma unroll
        for (int j = 0; j < 8; ++j) {
            float2 p = unpack2(acc[i][j]);
            ve[j] = fmaxf(p.x * ae + be, 0.0f);
            vo[j] = fmaxf(p.y * ao + bo, 0.0f);
        }
        size_t oe = ((size_t)b * 768 + ce) * TS_out + tbase;
        size_t oo = oe + TS_out;
        if (tbase + 7 < T_out) {
            *(float4*)&out[oe] = make_float4(ve[0], ve[1], ve[2], ve[3]);
            *(float4*)&out[oe + 4] = make_float4(ve[4], ve[5], ve[6], ve[7]);
            *(float4*)&out[oo] = make_float4(vo[0], vo[1], vo[2], vo[3]);
            *(float4*)&out[oo + 4] = make_float4(vo[4], vo[5], vo[6], vo[7]);
        } else {
#pragma unroll
            for (int j = 0; j < 8; ++j) {
                if (tbase + j < T_out) {
                    out[oe + j] = ve[j];
                    out[oo + j] = vo[j];
                }
            }
        }
    }
}

// ---------------------------------------------------------------------------
// 1x1 conv (w6) + bias + transpose to [B][T'][D]
// x: [B][768][512] (logical 511), w6t: [768][64], z: [B][511][64]
// ---------------------------------------------------------------------------
__global__ void conv6_kernel(const float* __restrict__ x,
                             const float* __restrict__ w6t,
                             const float* __restrict__ b6,
                             float* __restrict__ z) {
    __shared__ float xs[8][768];
    __shared__ float ws[64][64];
    const int b = blockIdx.y;
    const int t0 = blockIdx.x * 8;
    const int tid = threadIdx.x;

    for (int idx = tid; idx < 8 * 768; idx += 512) {
        int ci = idx >> 3, tl = idx & 7;
        int t = t0 + tl;
        xs[tl][ci] = (t < 511) ? x[((size_t)b * 768 + ci) * 512 + t] : 0.0f;
    }
    const int tl = tid >> 6;
    const int d = tid & 63;
    float acc = 0.0f;
    for (int c0 = 0; c0 < 768; c0 += 64) {
        __syncthreads();
        for (int idx = tid; idx < 64 * 64; idx += 512) {
            int cc = idx >> 6, dd = idx & 63;
            ws[cc][dd] = w6t[(size_t)(c0 + cc) * 64 + dd];
        }
        __syncthreads();
#pragma unroll
        for (int cc = 0; cc < 64; ++cc) acc = fmaf(xs[tl][c0 + cc], ws[cc][d], acc);
    }
    int t = t0 + tl;
    if (t < 511) z[((size_t)b * 511 + t) * 64 + d] = acc + b6[d];
}

// ---------------------------------------------------------------------------
// VQ init: code norms + zero counts/loss (must reset every launch for graphs)
// ---------------------------------------------------------------------------
__global__ void vq_init_kernel(const float* __restrict__ emb,
                               float* __restrict__ enorm,
                               float* __restrict__ counts,
                               float* __restrict__ loss) {
    int c = threadIdx.x;
    float s = 0.0f;
#pragma unroll
    for (int dd = 0; dd < 64; ++dd) {
        float e = emb[(size_t)c * 64 + dd];
        s = fmaf(e, e, s);
    }
    enorm[c] = s;
    counts[c] = 0.0f;
    if (c == 0) loss[0] = 0.0f;
}

// ---------------------------------------------------------------------------
// VQ: per-row argmin over 512 codes (D=64), straight-through output,
// loss partial + counts.  One thread per row, codebook chunked in smem.
// ---------------------------------------------------------------------------
__global__ void vq_kernel(const float* __restrict__ z,
                          const float* __restrict__ emb,
                          const float* __restrict__ enorm,
                          float* __restrict__ out,
                          float* __restrict__ loss,
                          float* __restrict__ counts) {
    __shared__ float sE[128 * 64];
    __shared__ float sN[128];
    __shared__ float red[128];
    const int tid = threadIdx.x;
    const int row = blockIdx.x * 128 + tid;
    const bool valid = row < 16352;

    float zr[64];
    if (valid) {
#pragma unroll
        for (int k = 0; k < 16; ++k)
            *(float4*)&zr[k * 4] = *(const float4*)&z[(size_t)row * 64 + k * 4];
    } else {
#pragma unroll
        for (int k = 0; k < 64; ++k) zr[k] = 0.0f;
    }

    float best = 3.4e38f;
    int bi = 0;
    for (int c0 = 0; c0 < 512; c0 += 128) {
        __syncthreads();
        for (int k = tid; k < 2048; k += 128)
            ((float4*)sE)[k] = ((const float4*)(emb + (size_t)c0 * 64))[k];
        sN[tid] = enorm[c0 + tid];
        __syncthreads();
        for (int c = 0; c < 128; ++c) {
            const float* e = &sE[c * 64];
            float dot = 0.0f;
#pragma unroll
            for (int dd = 0; dd < 64; ++dd) dot = fmaf(zr[dd], e[dd], dot);
            float dist = fmaf(-2.0f, dot, sN[c]);  // ||x||^2 const per row
            if (dist < best) { best = dist; bi = c0 + c; }
        }
    }

    float diff2 = 0.0f;
    if (valid) {
        const float* e = emb + (size_t)bi * 64;
#pragma unroll
        for (int dd = 0; dd < 64; ++dd) {
            float ev = e[dd];
            out[(size_t)row * 64 + dd] = ev;  // q_st forward value == quantized
            float df = zr[dd] - ev;
            diff2 = fmaf(df, df, diff2);
        }
        atomicAdd(&counts[bi], 1.0f);
    }
    red[tid] = diff2;
    __syncthreads();
    for (int s = 64; s > 0; s >>= 1) {
        if (tid < s) red[tid] += red[tid + s];
        __syncthreads();
    }
    if (tid == 0) atomicAdd(loss, red[0]);
}

// ---------------------------------------------------------------------------
// Finalize: loss scale + perplexity
// ---------------------------------------------------------------------------
__global__ void vq_final_kernel(const float* __restrict__ counts,
                                const float* __restrict__ loss,
                                float* __restrict__ out) {
    __shared__ float red[512];
    int tid = threadIdx.x;
    float avg = counts[tid] * (1.0f / 16352.0f);
    red[tid] = avg * logf(avg + 1e-10f);
    __syncthreads();
    for (int s = 256; s > 0; s >>= 1) {
        if (tid < s) red[tid] += red[tid + s];
        __syncthreads();
    }
    if (tid == 0) {
        out[1046528] = 0.25f * loss[0] * (1.0f / 1046528.0f);
        out[1046529] = expf(-red[0]);
    }
}

// ---------------------------------------------------------------------------
// kernel_launch
// Inputs (metadata order): mels, w1..w5, w6, b6, bn_gamma, bn_beta, bn_mean,
//                          bn_var, embedding
// Output: q_st [32,511,64] flat, then loss, then perplexity.
// ---------------------------------------------------------------------------
extern "C" void kernel_launch(void* const* d_in, const int* in_sizes, int n_in,
                              void* d_out, int out_size) {
    const float* mels = (const float*)d_in[0];
    const float* w1 = (const float*)d_in[1];
    const float* w2 = (const float*)d_in[2];
    const float* w3 = (const float*)d_in[3];
    const float* w4 = (const float*)d_in[4];
    const float* w5 = (const float*)d_in[5];
    const float* w6 = (const float*)d_in[6];
    const float* b6 = (const float*)d_in[7];
    const float* bng = (const float*)d_in[8];
    const float* bnb = (const float*)d_in[9];
    const float* bnm = (const float*)d_in[10];
    const float* bnv = (const float*)d_in[11];
    const float* emb = (const float*)d_in[12];
    float* out = (float*)d_out;

    float *bufA, *bufB, *wt, *w6t, *z, *enorm, *counts, *loss;
    cudaGetSymbolAddress((void**)&bufA, g_bufA);
    cudaGetSymbolAddress((void**)&bufB, g_bufB);
    cudaGetSymbolAddress((void**)&wt, g_wt);
    cudaGetSymbolAddress((void**)&w6t, g_w6t);
    cudaGetSymbolAddress((void**)&z, g_z);
    cudaGetSymbolAddress((void**)&enorm, g_enorm);
    cudaGetSymbolAddress((void**)&counts, g_counts);
    cudaGetSymbolAddress((void**)&loss, g_loss);

    // Layer 1: [32,80,1024] -> [32,768,1022] (pad to 1024)
    transpose_w_kernel<<<(3 * 80 * 768 + 255) / 256, 256>>>(w1, wt, 80, 3);
    conv_bn_relu_kernel<80, 3, 1, 0><<<dim3(8, 6, 32), 256>>>(
        mels, wt, bng + 0, bnb + 0, bnm + 0, bnv + 0, bufA, 1024, 1024, 1022, 1024);

    // Layer 2
    transpose_w_kernel<<<(3 * 768 * 768 + 255) / 256, 256>>>(w2, wt, 768, 3);
    conv_bn_relu_kernel<768, 3, 1, 1><<<dim3(8, 6, 32), 256>>>(
        bufA, wt, bng + 768, bnb + 768, bnm + 768, bnv + 768, bufB, 1022, 1024,
        1022, 1024);

    // Layer 3 (stride 2): -> T=511 (pad to 512)
    transpose_w_kernel<<<(4 * 768 * 768 + 255) / 256, 256>>>(w3, wt, 768, 4);
    conv_bn_relu_kernel<768, 4, 2, 1><<<dim3(4, 6, 32), 256>>>(
        bufB, wt, bng + 1536, bnb + 1536, bnm + 1536, bnv + 1536, bufA, 1022,
        1024, 511, 512);

    // Layer 4
    transpose_w_kernel<<<(3 * 768 * 768 + 255) / 256, 256>>>(w4, wt, 768, 3);
    conv_bn_relu_kernel<768, 3, 1, 1><<<dim3(4, 6, 32), 256>>>(
        bufA, wt, bng + 2304, bnb + 2304, bnm + 2304, bnv + 2304, bufB, 511, 512,
        511, 512);

    // Layer 5
    transpose_w_kernel<<<(3 * 768 * 768 + 255) / 256, 256>>>(w5, wt, 768, 3);
    conv_bn_relu_kernel<768, 3, 1, 1><<<dim3(4, 6, 32), 256>>>(
        bufB, wt, bng + 3072, bnb + 3072, bnm + 3072, bnv + 3072, bufA, 511, 512,
        511, 512);

    // 1x1 conv + transpose -> z [32,511,64]
    transpose_w6_kernel<<<(768 * 64 + 255) / 256, 256>>>(w6, w6t);
    conv6_kernel<<<dim3(64, 32), 512>>>(bufA, w6t, b6, z);

    // VQ
    vq_init_kernel<<<1, 512>>>(emb, enorm, counts, loss);
    vq_kernel<<<128, 128>>>(z, emb, enorm, out, loss, counts);
    vq_final_kernel<<<1, 512>>>(counts, loss, out);
}

// round 4
// speedup vs baseline: 1.1066x; 1.1066x over previous
#include <cuda_runtime.h>
#include <cuda_bf16.h>
#include <cstdint>

// ---------------------------------------------------------------------------
// Scratch (static __device__ arrays; no allocation allowed)
// ---------------------------------------------------------------------------
__device__ float g_bufA[32u * 768u * 1024u];   // ~100 MB ping
__device__ float g_bufB[32u * 768u * 1024u];   // ~100 MB pong
__device__ float g_wt[4u * 768u * 768u];       // transposed weights [tap][ci][co]
__device__ float g_w6t[768u * 64u];            // w6 transposed [ci][d]
__device__ float g_z[32u * 511u * 64u];        // encoder output, [B][T'][D]
__device__ float g_enorm[512];
__device__ float g_counts[512];
__device__ float g_loss[1];

// ---------------------------------------------------------------------------
// f32x2 helpers (packed dual-FP32 FMA — 2x fp32 throughput on sm_103a)
// ---------------------------------------------------------------------------
__device__ __forceinline__ void fma2(unsigned long long& d,
                                     unsigned long long a,
                                     unsigned long long b) {
    asm("fma.rn.f32x2 %0, %1, %2, %0;" : "+l"(d) : "l"(a), "l"(b));
}
__device__ __forceinline__ float2 unpack2(unsigned long long v) {
    float2 r;
    asm("mov.b64 {%0, %1}, %2;" : "=f"(r.x), "=f"(r.y) : "l"(v));
    return r;
}

// ---------------------------------------------------------------------------
// Weight transpose: w[CO][CI][KS] -> wt[tap][ci][co]  (coalesced writes)
// ---------------------------------------------------------------------------
__global__ void transpose_w_kernel(const float* __restrict__ w,
                                   float* __restrict__ wt, int CI, int KS) {
    int total = 768 * CI * KS;
    int idx = blockIdx.x * 256 + threadIdx.x;
    if (idx >= total) return;
    int co = idx % 768;
    int r = idx / 768;
    int ci = r % CI;
    int tap = r / CI;
    wt[idx] = w[((size_t)co * CI + ci) * KS + tap];
}

__global__ void transpose_w6_kernel(const float* __restrict__ w6,
                                    float* __restrict__ w6t) {
    int idx = blockIdx.x * 256 + threadIdx.x;
    if (idx >= 768 * 64) return;
    int d = idx & 63;
    int ci = idx >> 6;
    w6t[idx] = w6[(size_t)d * 768 + ci];
}

// ---------------------------------------------------------------------------
// Conv1d + folded BN + ReLU, implicit GEMM.
// Tile: 128 co x 128 t per block, 256 threads, 8co x 8t outputs/thread as
// 4 co-pairs x 8 t packed f32x2 accumulators.
//
// R2 changes vs R1 (smem-crossbar bound -> fma-bound):
//  - B window hoisted per kk: (7*STRIDE+KS) duplicated entries loaded once
//    via LDS.128 vectors, reused across all taps.
//  - 16B-granular XOR swizzle on sB -> conflict-free vector loads.
//  - CHUNK=16 for K=3 layers (fewer barriers / less load exposure).
// ---------------------------------------------------------------------------
template <int CIN, int KS, int STRIDE, int PAD, int CHUNK>
__global__ void __launch_bounds__(256, 2)
conv_bn_relu_kernel(const float* __restrict__ x, const float* __restrict__ wt,
                    const float* __restrict__ gamma, const float* __restrict__ beta,
                    const float* __restrict__ mean, const float* __restrict__ var,
                    float* __restrict__ out,
                    int T_in, int TS_in, int T_out, int TS_out) {
    constexpr int SPAN  = 127 * STRIDE + KS;     // input entries per 128 outputs
    constexpr int SPANC = (SPAN + 1) / 2;        // 16B chunks per row
    constexpr int ROWC  = SPANC + 8;             // pad for swizzle reach
    constexpr int WENT  = 7 * STRIDE + KS;       // window entries per thread
    constexpr int WCH   = (WENT + 1) / 2;        // window chunks per thread
    constexpr int SH    = (STRIDE == 1) ? 2 : 3; // swizzle shift

    __shared__ __align__(16) float  sA[CHUNK][KS * 128];   // [kk][tap*128+co]
    __shared__ __align__(16) float2 sB[CHUNK][ROWC * 2];   // dup entries, swizzled

    const int b    = blockIdx.z;
    const int co0  = blockIdx.y * 128;
    const int t0   = blockIdx.x * 128;
    const int tid  = threadIdx.x;
    const int warp = tid >> 5;
    const int lane = tid & 31;
    const int tm   = tid >> 4;   // 0..15 -> co group of 8
    const int tn   = tid & 15;   // 0..15 -> t  group of 8

    unsigned long long acc[4][8];
#pragma unroll
    for (int i = 0; i < 4; ++i)
#pragma unroll
        for (int j = 0; j < 8; ++j) acc[i][j] = 0ull;

    const float* xb = x + (size_t)b * CIN * TS_in;
    const int tin_start = t0 * STRIDE - PAD;
    const int qbase = tn * 4 * STRIDE;           // first window chunk (logical)

    for (int ci0 = 0; ci0 < CIN; ci0 += CHUNK) {
        __syncthreads();
#pragma unroll
        for (int r = warp; r < CHUNK; r += 8) {
            const int ci = ci0 + r;
#pragma unroll
            for (int tap = 0; tap < KS; ++tap) {
                float4 v = *(const float4*)(wt + ((size_t)(tap * CIN + ci)) * 768 +
                                            co0 + lane * 4);
                *(float4*)&sA[r][tap * 128 + lane * 4] = v;
            }
            const float* xr = xb + (size_t)ci * TS_in;
            for (int p = lane; p < SPAN; p += 32) {
                int tin = tin_start + p;
                float v = (tin >= 0 && tin < T_in) ? xr[tin] : 0.0f;
                int q  = p >> 1;
                int qp = q ^ ((q >> SH) & 7);
                sB[r][qp * 2 + (p & 1)] = make_float2(v, v);
            }
        }
        __syncthreads();

#pragma unroll
        for (int kk = 0; kk < CHUNK; ++kk) {
            // Hoisted B window: WENT duplicated entries, vector loads.
            unsigned long long bw[WCH * 2];
#pragma unroll
            for (int c = 0; c < WCH; ++c) {
                int q  = qbase + c;
                int qp = q ^ ((q >> SH) & 7);
                ulonglong2 v = *(const ulonglong2*)&sB[kk][qp * 2];
                bw[2 * c]     = v.x;
                bw[2 * c + 1] = v.y;
            }
#pragma unroll
            for (int tap = 0; tap < KS; ++tap) {
                ulonglong2 A0 = *(const ulonglong2*)&sA[kk][tap * 128 + tm * 8];
                ulonglong2 A1 = *(const ulonglong2*)&sA[kk][tap * 128 + tm * 8 + 4];
                const unsigned long long ap0 = A0.x, ap1 = A0.y, ap2 = A1.x, ap3 = A1.y;
#pragma unroll
                for (int j = 0; j < 8; ++j) {
                    unsigned long long bv = bw[tap + j * STRIDE];
                    fma2(acc[0][j], ap0, bv);
                    fma2(acc[1][j], ap1, bv);
                    fma2(acc[2][j], ap2, bv);
                    fma2(acc[3][j], ap3, bv);
                }
            }
        }
    }

    // Epilogue: folded BN + ReLU, vectorized stores (TS_out keeps 16B alignment)
    const int tbase = t0 + tn * 8;
#pragma unroll
    for (int i = 0; i < 4; ++i) {
        const int ce = co0 + tm * 8 + 2 * i;
        const float ae = gamma[ce] / sqrtf(var[ce] + 1e-5f);
        const float be = beta[ce] - mean[ce] * ae;
        const float ao = gamma[ce + 1] / sqrtf(var[ce + 1] + 1e-5f);
        const float bo = beta[ce + 1] - mean[ce + 1] * ao;
        float ve[8], vo[8];
#pragma unroll
        for (int j = 0; j < 8; ++j) {
            float2 p = unpack2(acc[i][j]);
            ve[j] = fmaxf(p.x * ae + be, 0.0f);
            vo[j] = fmaxf(p.y * ao + bo, 0.0f);
        }
        size_t oe = ((size_t)b * 768 + ce) * TS_out + tbase;
        size_t oo = oe + TS_out;
        if (tbase + 7 < T_out) {
            *(float4*)&out[oe] = make_float4(ve[0], ve[1], ve[2], ve[3]);
            *(float4*)&out[oe + 4] = make_float4(ve[4], ve[5], ve[6], ve[7]);
            *(float4*)&out[oo] = make_float4(vo[0], vo[1], vo[2], vo[3]);
            *(float4*)&out[oo + 4] = make_float4(vo[4], vo[5], vo[6], vo[7]);
        } else {
#pragma unroll
            for (int j = 0; j < 8; ++j) {
                if (tbase + j < T_out) {
                    out[oe + j] = ve[j];
                    out[oo + j] = vo[j];
                }
            }
        }
    }
}

// ---------------------------------------------------------------------------
// 1x1 conv (w6) + bias + transpose to [B][T'][D]
// ---------------------------------------------------------------------------
__global__ void conv6_kernel(const float* __restrict__ x,
                             const float* __restrict__ w6t,
                             const float* __restrict__ b6,
                             float* __restrict__ z) {
    __shared__ float xs[8][768];
    __shared__ float ws[64][64];
    const int b = blockIdx.y;
    const int t0 = blockIdx.x * 8;
    const int tid = threadIdx.x;

    for (int idx = tid; idx < 8 * 768; idx += 512) {
        int ci = idx >> 3, tl = idx & 7;
        int t = t0 + tl;
        xs[tl][ci] = (t < 511) ? x[((size_t)b * 768 + ci) * 512 + t] : 0.0f;
    }
    const int tl = tid >> 6;
    const int d = tid & 63;
    float acc = 0.0f;
    for (int c0 = 0; c0 < 768; c0 += 64) {
        __syncthreads();
        for (int idx = tid; idx < 64 * 64; idx += 512) {
            int cc = idx >> 6, dd = idx & 63;
            ws[cc][dd] = w6t[(size_t)(c0 + cc) * 64 + dd];
        }
        __syncthreads();
#pragma unroll
        for (int cc = 0; cc < 64; ++cc) acc = fmaf(xs[tl][c0 + cc], ws[cc][d], acc);
    }
    int t = t0 + tl;
    if (t < 511) z[((size_t)b * 511 + t) * 64 + d] = acc + b6[d];
}

// ---------------------------------------------------------------------------
// VQ init: code norms + zero counts/loss (must reset every launch for graphs)
// ---------------------------------------------------------------------------
__global__ void vq_init_kernel(const float* __restrict__ emb,
                               float* __restrict__ enorm,
                               float* __restrict__ counts,
                               float* __restrict__ loss) {
    int c = threadIdx.x;
    float s = 0.0f;
#pragma unroll
    for (int dd = 0; dd < 64; ++dd) {
        float e = emb[(size_t)c * 64 + dd];
        s = fmaf(e, e, s);
    }
    enorm[c] = s;
    counts[c] = 0.0f;
    if (c == 0) loss[0] = 0.0f;
}

// ---------------------------------------------------------------------------
// VQ: per-row argmin over 512 codes (D=64), straight-through output,
// loss partial + counts.
// ---------------------------------------------------------------------------
__global__ void vq_kernel(const float* __restrict__ z,
                          const float* __restrict__ emb,
                          const float* __restrict__ enorm,
                          float* __restrict__ out,
                          float* __restrict__ loss,
                          float* __restrict__ counts) {
    __shared__ float sE[128 * 64];
    __shared__ float sN[128];
    __shared__ float red[128];
    const int tid = threadIdx.x;
    const int row = blockIdx.x * 128 + tid;
    const bool valid = row < 16352;

    float zr[64];
    if (valid) {
#pragma unroll
        for (int k = 0; k < 16; ++k)
            *(float4*)&zr[k * 4] = *(const float4*)&z[(size_t)row * 64 + k * 4];
    } else {
#pragma unroll
        for (int k = 0; k < 64; ++k) zr[k] = 0.0f;
    }

    float best = 3.4e38f;
    int bi = 0;
    for (int c0 = 0; c0 < 512; c0 += 128) {
        __syncthreads();
        for (int k = tid; k < 2048; k += 128)
            ((float4*)sE)[k] = ((const float4*)(emb + (size_t)c0 * 64))[k];
        sN[tid] = enorm[c0 + tid];
        __syncthreads();
        for (int c = 0; c < 128; ++c) {
            const float* e = &sE[c * 64];
            float dot = 0.0f;
#pragma unroll
            for (int dd = 0; dd < 64; ++dd) dot = fmaf(zr[dd], e[dd], dot);
            float dist = fmaf(-2.0f, dot, sN[c]);
            if (dist < best) { best = dist; bi = c0 + c; }
        }
    }

    float diff2 = 0.0f;
    if (valid) {
        const float* e = emb + (size_t)bi * 64;
#pragma unroll
        for (int dd = 0; dd < 64; ++dd) {
            float ev = e[dd];
            out[(size_t)row * 64 + dd] = ev;
            float df = zr[dd] - ev;
            diff2 = fmaf(df, df, diff2);
        }
        atomicAdd(&counts[bi], 1.0f);
    }
    red[tid] = diff2;
    __syncthreads();
    for (int s = 64; s > 0; s >>= 1) {
        if (tid < s) red[tid] += red[tid + s];
        __syncthreads();
    }
    if (tid == 0) atomicAdd(loss, red[0]);
}

// ---------------------------------------------------------------------------
// Finalize: loss scale + perplexity
// ---------------------------------------------------------------------------
__global__ void vq_final_kernel(const float* __restrict__ counts,
                                const float* __restrict__ loss,
                                float* __restrict__ out) {
    __shared__ float red[512];
    int tid = threadIdx.x;
    float avg = counts[tid] * (1.0f / 16352.0f);
    red[tid] = avg * logf(avg + 1e-10f);
    __syncthreads();
    for (int s = 256; s > 0; s >>= 1) {
        if (tid < s) red[tid] += red[tid + s];
        __syncthreads();
    }
    if (tid == 0) {
        out[1046528] = 0.25f * loss[0] * (1.0f / 1046528.0f);
        out[1046529] = expf(-red[0]);
    }
}

// ---------------------------------------------------------------------------
// kernel_launch
// ---------------------------------------------------------------------------
extern "C" void kernel_launch(void* const* d_in, const int* in_sizes, int n_in,
                              void* d_out, int out_size) {
    const float* mels = (const float*)d_in[0];
    const float* w1 = (const float*)d_in[1];
    const float* w2 = (const float*)d_in[2];
    const float* w3 = (const float*)d_in[3];
    const float* w4 = (const float*)d_in[4];
    const float* w5 = (const float*)d_in[5];
    const float* w6 = (const float*)d_in[6];
    const float* b6 = (const float*)d_in[7];
    const float* bng = (const float*)d_in[8];
    const float* bnb = (const float*)d_in[9];
    const float* bnm = (const float*)d_in[10];
    const float* bnv = (const float*)d_in[11];
    const float* emb = (const float*)d_in[12];
    float* out = (float*)d_out;

    float *bufA, *bufB, *wt, *w6t, *z, *enorm, *counts, *loss;
    cudaGetSymbolAddress((void**)&bufA, g_bufA);
    cudaGetSymbolAddress((void**)&bufB, g_bufB);
    cudaGetSymbolAddress((void**)&wt, g_wt);
    cudaGetSymbolAddress((void**)&w6t, g_w6t);
    cudaGetSymbolAddress((void**)&z, g_z);
    cudaGetSymbolAddress((void**)&enorm, g_enorm);
    cudaGetSymbolAddress((void**)&counts, g_counts);
    cudaGetSymbolAddress((void**)&loss, g_loss);

    // Layer 1: [32,80,1024] -> [32,768,1022] (pad to 1024)
    transpose_w_kernel<<<(3 * 80 * 768 + 255) / 256, 256>>>(w1, wt, 80, 3);
    conv_bn_relu_kernel<80, 3, 1, 0, 16><<<dim3(8, 6, 32), 256>>>(
        mels, wt, bng + 0, bnb + 0, bnm + 0, bnv + 0, bufA, 1024, 1024, 1022, 1024);

    // Layer 2
    transpose_w_kernel<<<(3 * 768 * 768 + 255) / 256, 256>>>(w2, wt, 768, 3);
    conv_bn_relu_kernel<768, 3, 1, 1, 16><<<dim3(8, 6, 32), 256>>>(
        bufA, wt, bng + 768, bnb + 768, bnm + 768, bnv + 768, bufB, 1022, 1024,
        1022, 1024);

    // Layer 3 (stride 2): -> T=511 (pad to 512)
    transpose_w_kernel<<<(4 * 768 * 768 + 255) / 256, 256>>>(w3, wt, 768, 4);
    conv_bn_relu_kernel<768, 4, 2, 1, 8><<<dim3(4, 6, 32), 256>>>(
        bufB, wt, bng + 1536, bnb + 1536, bnm + 1536, bnv + 1536, bufA, 1022,
        1024, 511, 512);

    // Layer 4
    transpose_w_kernel<<<(3 * 768 * 768 + 255) / 256, 256>>>(w4, wt, 768, 3);
    conv_bn_relu_kernel<768, 3, 1, 1, 16><<<dim3(4, 6, 32), 256>>>(
        bufA, wt, bng + 2304, bnb + 2304, bnm + 2304, bnv + 2304, bufB, 511, 512,
        511, 512);

    // Layer 5
    transpose_w_kernel<<<(3 * 768 * 768 + 255) / 256, 256>>>(w5, wt, 768, 3);
    conv_bn_relu_kernel<768, 3, 1, 1, 16><<<dim3(4, 6, 32), 256>>>(
        bufB, wt, bng + 3072, bnb + 3072, bnm + 3072, bnv + 3072, bufA, 511, 512,
        511, 512);

    // 1x1 conv + transpose -> z [32,511,64]
    transpose_w6_kernel<<<(768 * 64 + 255) / 256, 256>>>(w6, w6t);
    conv6_kernel<<<dim3(64, 32), 512>>>(bufA, w6t, b6, z);

    // VQ
    vq_init_kernel<<<1, 512>>>(emb, enorm, counts, loss);
    vq_kernel<<<128, 128>>>(z, emb, enorm, out, loss, counts);
    vq_final_kernel<<<1, 512>>>(counts, loss, out);
}

// round 7
// speedup vs baseline: 2.2059x; 1.9933x over previous
#include <cuda_runtime.h>
#include <cuda_bf16.h>
#include <cstdint>

// ---------------------------------------------------------------------------
// Scratch (static __device__ arrays; no allocation allowed)
// ---------------------------------------------------------------------------
__device__ float g_bufA[32u * 768u * 1024u];   // ~100 MB ping
__device__ float g_bufB[32u * 768u * 1024u];   // ~100 MB pong
__device__ __nv_bfloat16 g_wsplit[3u * 768u * 3072u];  // split weights [p][co][KPAD]
__device__ float g_w6t[768u * 64u];
__device__ float g_z[32u * 511u * 64u];
__device__ float g_enorm[512];
__device__ float g_counts[512];
__device__ float g_loss[1];

// ---------------------------------------------------------------------------
// Helpers (baseline PTX only — compute_103-safe: ldmatrix + mma.sync)
// ---------------------------------------------------------------------------
__device__ __forceinline__ uint32_t smem_u32(const void* p) {
    uint32_t a;
    asm("{ .reg .u64 t; cvta.to.shared.u64 t, %1; cvt.u32.u64 %0, t; }"
        : "=r"(a) : "l"(p));
    return a;
}
#define SWZ128(b) ((b) ^ (((b) >> 3) & 0x70))

#define LDSM4(r0, r1, r2, r3, addr)                                         \
    asm volatile("ldmatrix.sync.aligned.m8n8.x4.shared.b16 {%0,%1,%2,%3}, [%4];" \
                 : "=r"(r0), "=r"(r1), "=r"(r2), "=r"(r3) : "r"(addr))

#define MMA16816(c, a, b0, b1)                                              \
    asm volatile(                                                           \
        "mma.sync.aligned.m16n8k16.row.col.f32.bf16.bf16.f32 "              \
        "{%0,%1,%2,%3}, {%4,%5,%6,%7}, {%8,%9}, {%0,%1,%2,%3};"             \
        : "+f"((c)[0]), "+f"((c)[1]), "+f"((c)[2]), "+f"((c)[3])            \
        : "r"((a)[0]), "r"((a)[1]), "r"((a)[2]), "r"((a)[3]),               \
          "r"(b0), "r"(b1))

// ---------------------------------------------------------------------------
// Weight split: w[co][ci][tap] fp32 -> 3 bf16 planes [p][co][KPAD], k=ci*KS+tap
// ---------------------------------------------------------------------------
__global__ void split_w_kernel(const float* __restrict__ w,
                               __nv_bfloat16* __restrict__ w3,
                               int CIN, int KS, int KPAD) {
    int idx = blockIdx.x * 256 + threadIdx.x;
    int total = 768 * KPAD;
    if (idx >= total) return;
    int k = idx % KPAD;
    int co = idx / KPAD;
    float v = (k < CIN * KS) ? w[(size_t)co * CIN * KS + k] : 0.0f;
    __nv_bfloat16 h = __float2bfloat16(v);
    float vh = __bfloat162float(h);
    __nv_bfloat16 m = __float2bfloat16(v - vh);
    float vm = __bfloat162float(m);
    __nv_bfloat16 l = __float2bfloat16(v - vh - vm);
    w3[idx] = h;
    w3[total + idx] = m;
    w3[2 * total + idx] = l;
}

// ---------------------------------------------------------------------------
// Conv1d + BN + ReLU: warp-level bf16 mma.sync (HMMA), 3-way split, 6 products.
// Block tile: 128 co x 128 t, 8 warps (warp tile 64x32), K-chunks of 64.
// smem: [inv|bb 1KB][A0 A1 A2 B0 B1 B2 tiles 16KB each][fp32 staging]
// Tiles: rows of 64 bf16 (128B), SW128 swizzle at 16B granularity.
// ---------------------------------------------------------------------------
template <int CIN, int KS, int STRIDE, int PAD>
__global__ void __launch_bounds__(256, 2)
conv_mma_kernel(const float* __restrict__ x, const __nv_bfloat16* __restrict__ w3,
                const float* __restrict__ gamma, const float* __restrict__ beta,
                const float* __restrict__ mean, const float* __restrict__ var,
                float* __restrict__ out,
                int T_in, int TS_in, int T_out, int TS_out) {
    constexpr int KPAD = ((CIN * KS + 63) / 64) * 64;
    constexpr int NCHUNK = KPAD / 64;
    constexpr int SPAN = 127 * STRIDE + KS;
    constexpr int SPAN_AL = SPAN + 2;
    constexpr int HALVES = (STRIDE == 2) ? 2 : 1;   // K4/stride2: 2 halves (smem)
    constexpr int KH = 64 / HALVES;                 // k per half
    constexpr int STG_ROWS = (KS == 3) ? 22 : 8;    // ci rows staged per half
    constexpr int TILE = 16384;                     // 128 rows x 128B
    constexpr int TILES_OFF = 1024;
    constexpr int STG_OFF = TILES_OFF + 6 * TILE;

    extern __shared__ __align__(16) char smem[];
    float* sInv = (float*)smem;
    float* sBb = (float*)(smem + 512);
    float* stg = (float*)(smem + STG_OFF);
    const uint32_t tilesBase = smem_u32(smem + TILES_OFF);

    const int b = blockIdx.z;
    const int co0 = blockIdx.y * 128;
    const int t0 = blockIdx.x * 128;
    const int tid = threadIdx.x;
    const int warp = tid >> 5;
    const int lane = tid & 31;
    const int wm = warp & 1;   // 0..1 -> 64 co rows
    const int wn = warp >> 1;  // 0..3 -> 32 t cols

    // BN constants for this co-slab
    if (tid < 128) {
        int co = co0 + tid;
        float iv = gamma[co] * rsqrtf(var[co] + 1e-5f);
        sInv[tid] = iv;
        sBb[tid] = beta[co] - mean[co] * iv;
    }

    float acc[4][4][4];
#pragma unroll
    for (int mb = 0; mb < 4; ++mb)
#pragma unroll
        for (int nb = 0; nb < 4; ++nb)
#pragma unroll
            for (int e = 0; e < 4; ++e) acc[mb][nb][e] = 0.0f;

    // ldmatrix per-lane address components
    const int q = lane >> 3, r8 = lane & 7;
    const uint32_t xr = (uint32_t)r8 << 4;
    const uint32_t kha = (uint32_t)(q >> 1) << 4;   // A: khalf from quadrant hi bit
    const uint32_t khb = (uint32_t)(q & 1) << 4;    // B: khalf from quadrant lo bit
    const uint32_t aRow = tilesBase + (uint32_t)((wm * 64 + (q & 1) * 8 + r8) << 7);
    const uint32_t bRow = tilesBase + 3 * TILE +
                          (uint32_t)((wn * 32 + (q >> 1) * 8 + r8) << 7);

    const float* xb = x + (size_t)b * CIN * TS_in;
    const int tin0 = t0 * STRIDE - PAD;

#pragma unroll 1
    for (int c = 0; c < NCHUNK; ++c) {
        __syncthreads();  // previous compute done -> tiles + staging free

        // ---- A fill: 3 planes x 128 rows x 8 x 16B = 3072 tasks ----
#pragma unroll
        for (int i = 0; i < 12; ++i) {
            int task = tid + i * 256;
            int gg = task & 7;
            int row = (task >> 3) & 127;
            int p = task >> 10;
            uint4 v = *(const uint4*)(w3 + ((size_t)(p * 768 + co0 + row)) * KPAD +
                                      c * 64 + gg * 8);
            uint32_t byte = (uint32_t)(row << 7) + (uint32_t)(gg << 4);
            *(uint4*)(smem + TILES_OFF + p * TILE + SWZ128(byte)) = v;
        }

        // ---- B fill: stage fp32 rows, then im2col + 3-way split ----
#pragma unroll
        for (int h = 0; h < HALVES; ++h) {
            const int kb = c * 64 + h * KH;
            const int ci_lo = kb / KS;
            if (h > 0) __syncthreads();   // staging reuse
            for (int r = warp; r < STG_ROWS; r += 8) {
                int ci = ci_lo + r;
                const float* xr2 = xb + (size_t)ci * TS_in;
                for (int p = lane; p < SPAN; p += 32) {
                    int tin = tin0 + p;
                    float v = (ci < CIN && tin >= 0 && tin < T_in) ? xr2[tin] : 0.0f;
                    stg[r * SPAN_AL + p] = v;
                }
            }
            __syncthreads();
#pragma unroll
            for (int i = 0; i < KH / 16; ++i) {   // 128 t x (KH/8) kgroups tasks
                int tt = tid + i * 256;
                int t = tt & 127;
                int kg = h * (KH / 8) + (tt >> 7);
                union { __nv_bfloat16 e[8]; uint4 v; } ph, pm, pl;
#pragma unroll
                for (int j = 0; j < 8; ++j) {
                    int k = c * 64 + kg * 8 + j;
                    int ci = k / KS;
                    int tap = k - ci * KS;
                    float v = stg[(ci - ci_lo) * SPAN_AL + t * STRIDE + tap];
                    __nv_bfloat16 bh = __float2bfloat16(v);
                    float vh = __bfloat162float(bh);
                    __nv_bfloat16 bm = __float2bfloat16(v - vh);
                    float vm = __bfloat162float(bm);
                    __nv_bfloat16 bl = __float2bfloat16(v - vh - vm);
                    ph.e[j] = bh; pm.e[j] = bm; pl.e[j] = bl;
                }
                uint32_t sw = SWZ128((uint32_t)(t << 7) + (uint32_t)(kg << 4));
                *(uint4*)(smem + TILES_OFF + 3 * TILE + sw) = ph.v;
                *(uint4*)(smem + TILES_OFF + 4 * TILE + sw) = pm.v;
                *(uint4*)(smem + TILES_OFF + 5 * TILE + sw) = pl.v;
            }
        }
        __syncthreads();

        // ---- Compute: 4 k16 steps x 6 split products x 16 mma ----
#pragma unroll 1
        for (int ks = 0; ks < 4; ++ks) {
            const uint32_t koA = (((uint32_t)ks << 5) + kha) ^ xr;
            const uint32_t koB = (((uint32_t)ks << 5) + khb) ^ xr;
            uint32_t a[4][4], bf[4][2];

#define LOAD_A(pa)                                                          \
    {                                                                       \
        _Pragma("unroll") for (int mb = 0; mb < 4; ++mb) {                  \
            uint32_t ad = aRow + (pa) * TILE + mb * 2048 + koA;             \
            LDSM4(a[mb][0], a[mb][1], a[mb][2], a[mb][3], ad);              \
        }                                                                   \
    }
#define LOAD_B(pb)                                                          \
    {                                                                       \
        _Pragma("unroll") for (int jj = 0; jj < 2; ++jj) {                  \
            uint32_t bd = bRow + (pb) * TILE + jj * 2048 + koB;             \
            LDSM4(bf[2 * jj][0], bf[2 * jj][1], bf[2 * jj + 1][0],          \
                  bf[2 * jj + 1][1], bd);                                   \
        }                                                                   \
    }
#define DO_MMA()                                                            \
    {                                                                       \
        _Pragma("unroll") for (int mb = 0; mb < 4; ++mb)                    \
            _Pragma("unroll") for (int nb = 0; nb < 4; ++nb)                \
                MMA16816(acc[mb][nb], a[mb], bf[nb][0], bf[nb][1]);         \
    }
            LOAD_A(0); LOAD_B(0); DO_MMA();   // hh
            LOAD_B(1); DO_MMA();              // hm
            LOAD_B(2); DO_MMA();              // hl
            LOAD_A(1); LOAD_B(0); DO_MMA();   // mh
            LOAD_B(1); DO_MMA();              // mm
            LOAD_A(2); LOAD_B(0); DO_MMA();   // lh
#undef LOAD_A
#undef LOAD_B
#undef DO_MMA
        }
    }

    // ---- Epilogue: BN + ReLU from fragments, float2 stores (padded out) ----
    const int colb = t0 + wn * 32 + (lane & 3) * 2;
#pragma unroll
    for (int mb = 0; mb < 4; ++mb) {
        const int row0 = wm * 64 + mb * 16 + (lane >> 2);
        const float i0 = sInv[row0], b0 = sBb[row0];
        const float i1 = sInv[row0 + 8], b1 = sBb[row0 + 8];
        float* o0 = out + ((size_t)b * 768 + co0 + row0) * TS_out + colb;
        float* o1 = o0 + (size_t)8 * TS_out;
#pragma unroll
        for (int nb = 0; nb < 4; ++nb) {
            float2 v0, v1;
            v0.x = fmaxf(acc[mb][nb][0] * i0 + b0, 0.0f);
            v0.y = fmaxf(acc[mb][nb][1] * i0 + b0, 0.0f);
            v1.x = fmaxf(acc[mb][nb][2] * i1 + b1, 0.0f);
            v1.y = fmaxf(acc[mb][nb][3] * i1 + b1, 0.0f);
            *(float2*)(o0 + nb * 8) = v0;
            *(float2*)(o1 + nb * 8) = v1;
        }
    }
}

// ---------------------------------------------------------------------------
// 1x1 conv (w6) + bias + transpose to [B][T'][D]
// ---------------------------------------------------------------------------
__global__ void transpose_w6_kernel(const float* __restrict__ w6,
                                    float* __restrict__ w6t) {
    int idx = blockIdx.x * 256 + threadIdx.x;
    if (idx >= 768 * 64) return;
    int d = idx & 63;
    int ci = idx >> 6;
    w6t[idx] = w6[(size_t)d * 768 + ci];
}

__global__ void conv6_kernel(const float* __restrict__ x,
                             const float* __restrict__ w6t,
                             const float* __restrict__ b6,
                             float* __restrict__ z) {
    __shared__ float xs[8][768];
    __shared__ float ws[64][64];
    const int b = blockIdx.y;
    const int t0 = blockIdx.x * 8;
    const int tid = threadIdx.x;

    for (int idx = tid; idx < 8 * 768; idx += 512) {
        int ci = idx >> 3, tl = idx & 7;
        int t = t0 + tl;
        xs[tl][ci] = (t < 511) ? x[((size_t)b * 768 + ci) * 512 + t] : 0.0f;
    }
    const int tl = tid >> 6;
    const int d = tid & 63;
    float acc = 0.0f;
    for (int c0 = 0; c0 < 768; c0 += 64) {
        __syncthreads();
        for (int idx = tid; idx < 64 * 64; idx += 512) {
            int cc = idx >> 6, dd = idx & 63;
            ws[cc][dd] = w6t[(size_t)(c0 + cc) * 64 + dd];
        }
        __syncthreads();
#pragma unroll
        for (int cc = 0; cc < 64; ++cc) acc = fmaf(xs[tl][c0 + cc], ws[cc][d], acc);
    }
    int t = t0 + tl;
    if (t < 511) z[((size_t)b * 511 + t) * 64 + d] = acc + b6[d];
}

// ---------------------------------------------------------------------------
// VQ (unchanged from R4, passing)
// ---------------------------------------------------------------------------
__global__ void vq_init_kernel(const float* __restrict__ emb,
                               float* __restrict__ enorm,
                               float* __restrict__ counts,
                               float* __restrict__ loss) {
    int c = threadIdx.x;
    float s = 0.0f;
#pragma unroll
    for (int dd = 0; dd < 64; ++dd) {
        float e = emb[(size_t)c * 64 + dd];
        s = fmaf(e, e, s);
    }
    enorm[c] = s;
    counts[c] = 0.0f;
    if (c == 0) loss[0] = 0.0f;
}

__global__ void vq_kernel(const float* __restrict__ z,
                          const float* __restrict__ emb,
                          const float* __restrict__ enorm,
                          float* __restrict__ out,
                          float* __restrict__ loss,
                          float* __restrict__ counts) {
    __shared__ float sE[128 * 64];
    __shared__ float sN[128];
    __shared__ float red[128];
    const int tid = threadIdx.x;
    const int row = blockIdx.x * 128 + tid;
    const bool valid = row < 16352;

    float zr[64];
    if (valid) {
#pragma unroll
        for (int k = 0; k < 16; ++k)
            *(float4*)&zr[k * 4] = *(const float4*)&z[(size_t)row * 64 + k * 4];
    } else {
#pragma unroll
        for (int k = 0; k < 64; ++k) zr[k] = 0.0f;
    }

    float best = 3.4e38f;
    int bi = 0;
    for (int c0 = 0; c0 < 512; c0 += 128) {
        __syncthreads();
        for (int k = tid; k < 2048; k += 128)
            ((float4*)sE)[k] = ((const float4*)(emb + (size_t)c0 * 64))[k];
        sN[tid] = enorm[c0 + tid];
        __syncthreads();
        for (int c = 0; c < 128; ++c) {
            const float* e = &sE[c * 64];
            float dot = 0.0f;
#pragma unroll
            for (int dd = 0; dd < 64; ++dd) dot = fmaf(zr[dd], e[dd], dot);
            float dist = fmaf(-2.0f, dot, sN[c]);
            if (dist < best) { best = dist; bi = c0 + c; }
        }
    }

    float diff2 = 0.0f;
    if (valid) {
        const float* e = emb + (size_t)bi * 64;
#pragma unroll
        for (int dd = 0; dd < 64; ++dd) {
            float ev = e[dd];
            out[(size_t)row * 64 + dd] = ev;
            float df = zr[dd] - ev;
            diff2 = fmaf(df, df, diff2);
        }
        atomicAdd(&counts[bi], 1.0f);
    }
    red[tid] = diff2;
    __syncthreads();
    for (int s = 64; s > 0; s >>= 1) {
        if (tid < s) red[tid] += red[tid + s];
        __syncthreads();
    }
    if (tid == 0) atomicAdd(loss, red[0]);
}

__global__ void vq_final_kernel(const float* __restrict__ counts,
                                const float* __restrict__ loss,
                                float* __restrict__ out) {
    __shared__ float red[512];
    int tid = threadIdx.x;
    float avg = counts[tid] * (1.0f / 16352.0f);
    red[tid] = avg * logf(avg + 1e-10f);
    __syncthreads();
    for (int s = 256; s > 0; s >>= 1) {
        if (tid < s) red[tid] += red[tid + s];
        __syncthreads();
    }
    if (tid == 0) {
        out[1046528] = 0.25f * loss[0] * (1.0f / 1046528.0f);
        out[1046529] = expf(-red[0]);
    }
}

// ---------------------------------------------------------------------------
// kernel_launch
// ---------------------------------------------------------------------------
static inline int conv_smem(int KS, int STRIDE) {
    int span = 127 * STRIDE + KS;
    int stg_rows = (KS == 3) ? 22 : 8;
    return 1024 + 6 * 16384 + stg_rows * (span + 2) * 4;
}

extern "C" void kernel_launch(void* const* d_in, const int* in_sizes, int n_in,
                              void* d_out, int out_size) {
    const float* mels = (const float*)d_in[0];
    const float* w1 = (const float*)d_in[1];
    const float* w2 = (const float*)d_in[2];
    const float* w3 = (const float*)d_in[3];
    const float* w4 = (const float*)d_in[4];
    const float* w5 = (const float*)d_in[5];
    const float* w6 = (const float*)d_in[6];
    const float* b6 = (const float*)d_in[7];
    const float* bng = (const float*)d_in[8];
    const float* bnb = (const float*)d_in[9];
    const float* bnm = (const float*)d_in[10];
    const float* bnv = (const float*)d_in[11];
    const float* emb = (const float*)d_in[12];
    float* out = (float*)d_out;

    float *bufA, *bufB, *w6t, *z, *enorm, *counts, *loss;
    __nv_bfloat16* wsp;
    cudaGetSymbolAddress((void**)&bufA, g_bufA);
    cudaGetSymbolAddress((void**)&bufB, g_bufB);
    cudaGetSymbolAddress((void**)&wsp, g_wsplit);
    cudaGetSymbolAddress((void**)&w6t, g_w6t);
    cudaGetSymbolAddress((void**)&z, g_z);
    cudaGetSymbolAddress((void**)&enorm, g_enorm);
    cudaGetSymbolAddress((void**)&counts, g_counts);
    cudaGetSymbolAddress((void**)&loss, g_loss);

    const int smem_k3 = conv_smem(3, 1);   // layers 1,2,4,5
    const int smem_k4 = conv_smem(4, 2);   // layer 3
    cudaFuncSetAttribute(conv_mma_kernel<80, 3, 1, 0>,
                         cudaFuncAttributeMaxDynamicSharedMemorySize, smem_k3);
    cudaFuncSetAttribute(conv_mma_kernel<768, 3, 1, 1>,
                         cudaFuncAttributeMaxDynamicSharedMemorySize, smem_k3);
    cudaFuncSetAttribute(conv_mma_kernel<768, 4, 2, 1>,
                         cudaFuncAttributeMaxDynamicSharedMemorySize, smem_k4);

    // Layer 1: [32,80,1024] -> [32,768,1022] (pad to 1024)
    split_w_kernel<<<(768 * 256 + 255) / 256, 256>>>(w1, wsp, 80, 3, 256);
    conv_mma_kernel<80, 3, 1, 0><<<dim3(8, 6, 32), 256, smem_k3>>>(
        mels, wsp, bng + 0, bnb + 0, bnm + 0, bnv + 0, bufA, 1024, 1024, 1022, 1024);

    // Layer 2
    split_w_kernel<<<(768 * 2304 + 255) / 256, 256>>>(w2, wsp, 768, 3, 2304);
    conv_mma_kernel<768, 3, 1, 1><<<dim3(8, 6, 32), 256, smem_k3>>>(
        bufA, wsp, bng + 768, bnb + 768, bnm + 768, bnv + 768, bufB, 1022, 1024,
        1022, 1024);

    // Layer 3 (stride 2) -> T=511 (pad to 512)
    split_w_kernel<<<(768 * 3072 + 255) / 256, 256>>>(w3, wsp, 768, 4, 3072);
    conv_mma_kernel<768, 4, 2, 1><<<dim3(4, 6, 32), 256, smem_k4>>>(
        bufB, wsp, bng + 1536, bnb + 1536, bnm + 1536, bnv + 1536, bufA, 1022,
        1024, 511, 512);

    // Layer 4
    split_w_kernel<<<(768 * 2304 + 255) / 256, 256>>>(w4, wsp, 768, 3, 2304);
    conv_mma_kernel<768, 3, 1, 1><<<dim3(4, 6, 32), 256, smem_k3>>>(
        bufA, wsp, bng + 2304, bnb + 2304, bnm + 2304, bnv + 2304, bufB, 511, 512,
        511, 512);

    // Layer 5
    split_w_kernel<<<(768 * 2304 + 255) / 256, 256>>>(w5, wsp, 768, 3, 2304);
    conv_mma_kernel<768, 3, 1, 1><<<dim3(4, 6, 32), 256, smem_k3>>>(
        bufB, wsp, bng + 3072, bnb + 3072, bnm + 3072, bnv + 3072, bufA, 511, 512,
        511, 512);

    // 1x1 conv + transpose -> z [32,511,64]
    transpose_w6_kernel<<<(768 * 64 + 255) / 256, 256>>>(w6, w6t);
    conv6_kernel<<<dim3(64, 32), 512>>>(bufA, w6t, b6, z);

    // VQ
    vq_init_kernel<<<1, 512>>>(emb, enorm, counts, loss);
    vq_kernel<<<128, 128>>>(z, emb, enorm, out, loss, counts);
    vq_final_kernel<<<1, 512>>>(counts, loss, out);
}

// round 8
// speedup vs baseline: 2.6285x; 1.1916x over previous
#include <cuda_runtime.h>
#include <cuda_bf16.h>
#include <cstdint>

// ---------------------------------------------------------------------------
// Scratch (static __device__ arrays; no allocation allowed)
// ---------------------------------------------------------------------------
__device__ float g_bufA[32u * 768u * 1024u];   // ~100 MB ping
__device__ float g_bufB[32u * 768u * 1024u];   // ~100 MB pong
__device__ __nv_bfloat16 g_wsplit[3u * 768u * 3072u];   // [p][co][KPAD]
__device__ __nv_bfloat16 g_xs[3u * 3u * 32u * 768u * 1024u];  // [p][tap][b][ci][TSo] (453MB max)
__device__ float g_w6t[768u * 64u];
__device__ float g_z[32u * 511u * 64u];
__device__ float g_enorm[512];
__device__ float g_counts[512];
__device__ float g_loss[1];

// ---------------------------------------------------------------------------
// Helpers (baseline PTX only — compute_103-safe)
// ---------------------------------------------------------------------------
__device__ __forceinline__ uint32_t smem_u32(const void* p) {
    uint32_t a;
    asm("{ .reg .u64 t; cvta.to.shared.u64 t, %1; cvt.u32.u64 %0, t; }"
        : "=r"(a) : "l"(p));
    return a;
}

#define LDSM4(r0, r1, r2, r3, addr)                                              \
    asm volatile("ldmatrix.sync.aligned.m8n8.x4.shared.b16 {%0,%1,%2,%3}, [%4];" \
                 : "=r"(r0), "=r"(r1), "=r"(r2), "=r"(r3) : "r"(addr))

#define LDSM4T(r0, r1, r2, r3, addr)                                             \
    asm volatile("ldmatrix.sync.aligned.m8n8.x4.trans.shared.b16 {%0,%1,%2,%3}, [%4];" \
                 : "=r"(r0), "=r"(r1), "=r"(r2), "=r"(r3) : "r"(addr))

#define MMA16816(c, a, b0, b1)                                                   \
    asm volatile(                                                                \
        "mma.sync.aligned.m16n8k16.row.col.f32.bf16.bf16.f32 "                   \
        "{%0,%1,%2,%3}, {%4,%5,%6,%7}, {%8,%9}, {%0,%1,%2,%3};"                  \
        : "+f"((c)[0]), "+f"((c)[1]), "+f"((c)[2]), "+f"((c)[3])                 \
        : "r"((a)[0]), "r"((a)[1]), "r"((a)[2]), "r"((a)[3]),                    \
          "r"(b0), "r"(b1))

#define CP_ASYNC16(dst, src, sz)                                                 \
    asm volatile("cp.async.cg.shared.global [%0], [%1], 16, %2;"                 \
                 :: "r"(dst), "l"(src), "r"(sz) : "memory")
#define CP_COMMIT() asm volatile("cp.async.commit_group;" ::: "memory")
#define CP_WAIT0() asm volatile("cp.async.wait_group 0;" ::: "memory")

// ---------------------------------------------------------------------------
// Weight split: w[co][ci][tap] fp32 -> 3 bf16 planes [p][co][KPAD], k=ci*KS+tap
// ---------------------------------------------------------------------------
__global__ void split_w_kernel(const float* __restrict__ w,
                               __nv_bfloat16* __restrict__ w3,
                               int CIN, int KS, int KPAD) {
    int idx = blockIdx.x * 256 + threadIdx.x;
    int total = 768 * KPAD;
    if (idx >= total) return;
    int k = idx % KPAD;
    int co = idx / KPAD;
    float v = (k < CIN * KS) ? w[(size_t)co * CIN * KS + k] : 0.0f;
    __nv_bfloat16 h = __float2bfloat16(v);
    float vh = __bfloat162float(h);
    __nv_bfloat16 m = __float2bfloat16(v - vh);
    float vm = __bfloat162float(m);
    __nv_bfloat16 l = __float2bfloat16(v - vh - vm);
    w3[idx] = h;
    w3[total + idx] = m;
    w3[2 * total + idx] = l;
}

// ---------------------------------------------------------------------------
// Activation split + tap-expand: x fp32 [b][ci][TS_in] ->
// xs[p][tap][b][ci][TSo] bf16, xs[...][t] = split_p(x[ci][t*S + tap - PAD])
// ---------------------------------------------------------------------------
__global__ void xsplit_kernel(const float* __restrict__ x,
                              __nv_bfloat16* __restrict__ xs,
                              int CIN, int T_in, int TS_in, int TSo,
                              int S, int PAD, int KS, int total) {
    int idx = blockIdx.x * 256 + threadIdx.x;
    if (idx >= total) return;
    const int th = TSo >> 1;
    int t2 = idx % th;
    int r = idx / th;
    int ci = r % CIN;
    r /= CIN;
    int bb = r & 31;
    int tap = r >> 5;
    const float* xr = x + ((size_t)bb * CIN + ci) * TS_in;

    unsigned short hb[2], mb[2], lb[2];
#pragma unroll
    for (int j = 0; j < 2; ++j) {
        int t = 2 * t2 + j;
        int tin = t * S + tap - PAD;
        float v = (tin >= 0 && tin < T_in) ? xr[tin] : 0.0f;
        __nv_bfloat16 h = __float2bfloat16(v);
        float vh = __bfloat162float(h);
        __nv_bfloat16 m = __float2bfloat16(v - vh);
        float vm = __bfloat162float(m);
        __nv_bfloat16 l = __float2bfloat16(v - vh - vm);
        hb[j] = __bfloat16_as_ushort(h);
        mb[j] = __bfloat16_as_ushort(m);
        lb[j] = __bfloat16_as_ushort(l);
    }
    size_t pstride = (size_t)KS * 32 * CIN * TSo;
    size_t o = (((size_t)tap * 32 + bb) * CIN + ci) * TSo + 2 * t2;
    *(uint32_t*)(xs + o) = (uint32_t)hb[0] | ((uint32_t)hb[1] << 16);
    *(uint32_t*)(xs + o + pstride) = (uint32_t)mb[0] | ((uint32_t)mb[1] << 16);
    *(uint32_t*)(xs + o + 2 * pstride) = (uint32_t)lb[0] | ((uint32_t)lb[1] << 16);
}

// ---------------------------------------------------------------------------
// Conv + BN + ReLU: bf16 mma.sync, 3-way split (6 products), all-cp.async fill.
// Block tile 128co x 128t, 8 warps (64x32 each), K-chunks of 32, double buffer.
// smem: [BN 1KB][buf0: A0 A1 A2 B0 B1 B2 (8KB each)][buf1: same] = 97KB.
// A tile [128co][32k] rows 64B, swizzle col16 = (g + (r>>1)) & 3.
// B tile [32k][128t] rows 256B, swizzle col16 = tg ^ (k & 7), ldmatrix.trans.
// ---------------------------------------------------------------------------
template <int CIN, int KS>
__global__ void __launch_bounds__(256, 2)
conv_mma_kernel(const __nv_bfloat16* __restrict__ xs,
                const __nv_bfloat16* __restrict__ w3,
                const float* __restrict__ gamma, const float* __restrict__ beta,
                const float* __restrict__ mean, const float* __restrict__ var,
                float* __restrict__ out, int TSo, int T_out) {
    constexpr int KTOT = CIN * KS;
    constexpr int KPAD = ((KTOT + 31) / 32) * 32;
    constexpr int NCH = KPAD / 32;
    constexpr uint32_t BUFSZ = 6 * 8192;

    extern __shared__ __align__(16) char smem[];
    float* sInv = (float*)smem;
    float* sBb = (float*)(smem + 512);
    const uint32_t tilesBase = smem_u32(smem + 1024);

    const int b = blockIdx.z;
    const int co0 = blockIdx.y * 128;
    const int t0 = blockIdx.x * 128;
    const int tid = threadIdx.x;
    const int lane = tid & 31;
    const int warp = tid >> 5;
    const int wm = warp & 1;
    const int wn = warp >> 1;
    const int q = lane >> 3;
    const int r8 = lane & 7;

    if (tid < 128) {
        int co = co0 + tid;
        float iv = gamma[co] * rsqrtf(var[co] + 1e-5f);
        sInv[tid] = iv;
        sBb[tid] = beta[co] - mean[co] * iv;
    }

    float acc[4][4][4];
#pragma unroll
    for (int mb = 0; mb < 4; ++mb)
#pragma unroll
        for (int nb = 0; nb < 4; ++nb)
#pragma unroll
            for (int e = 0; e < 4; ++e) acc[mb][nb][e] = 0.0f;

    const size_t pstride = (size_t)KS * 32 * CIN * TSo;
    const __nv_bfloat16* xsb = xs + (size_t)b * CIN * TSo;  // + tap*32*CIN*TSo later

    // ---- fill chunk c into buffer bsel ----
    auto fill = [&](int c, uint32_t bsel) {
        const uint32_t tb = tilesBase + bsel * BUFSZ;
        // A: 3 planes x 128 rows x 4 x 16B
#pragma unroll
        for (int i = 0; i < 6; ++i) {
            int task = tid + i * 256;
            int g = task & 3;
            int row = (task >> 2) & 127;
            int p = task >> 9;
            uint32_t dst = tb + p * 8192 + (row << 6) + (((g + (row >> 1)) & 3) << 4);
            const __nv_bfloat16* src =
                w3 + ((size_t)(p * 768 + co0 + row)) * KPAD + c * 32 + g * 8;
            CP_ASYNC16(dst, src, 16);
        }
        // B: 3 planes x 32 k x 16 x 16B
#pragma unroll
        for (int i = 0; i < 6; ++i) {
            int task = tid + i * 256;
            int tg = task & 15;
            int k = (task >> 4) & 31;
            int p = task >> 9;
            int kg = c * 32 + k;
            int ci = kg / KS;
            int tap = kg - ci * KS;
            const __nv_bfloat16* src = xsb + p * 3 * pstride / 3 +  // p*pstride
                                       (size_t)p * 0;               // (see below)
            src = xs + (size_t)p * pstride +
                  (((size_t)tap * 32 + b) * CIN + ci) * TSo + t0 + tg * 8;
            uint32_t dst = tb + 24576 + p * 8192 + (k << 8) + ((tg ^ (k & 7)) << 4);
            int sz = (kg < KTOT) ? 16 : 0;
            CP_ASYNC16(dst, src, sz);
        }
        CP_COMMIT();
    };

    fill(0, 0);

#pragma unroll 1
    for (int c = 0; c < NCH; ++c) {
        CP_WAIT0();
        __syncthreads();
        if (c + 1 < NCH) fill(c + 1, (c + 1) & 1);
        const uint32_t tb = tilesBase + (uint32_t)(c & 1) * BUFSZ;

#pragma unroll
        for (int ks = 0; ks < 2; ++ks) {
            // B fragments: all 3 planes (n=32, k=16 each)
            uint32_t bfr[3][4][2];
#pragma unroll
            for (int p = 0; p < 3; ++p) {
#pragma unroll
                for (int jj = 0; jj < 2; ++jj) {
                    uint32_t k = ks * 16 + (q & 1) * 8 + r8;
                    uint32_t tg = wn * 4 + 2 * jj + (q >> 1);
                    uint32_t ad = tb + 24576 + p * 8192 + (k << 8) +
                                  ((tg ^ (k & 7)) << 4);
                    LDSM4T(bfr[p][2 * jj][0], bfr[p][2 * jj][1],
                           bfr[p][2 * jj + 1][0], bfr[p][2 * jj + 1][1], ad);
                }
            }
            // A planes, products: A0x{B0,B1,B2}, A1x{B0,B1}, A2x{B0}
#pragma unroll
            for (int pa = 0; pa < 3; ++pa) {
                uint32_t a[4][4];
#pragma unroll
                for (int mb = 0; mb < 4; ++mb) {
                    uint32_t row = wm * 64 + mb * 16 + (q & 1) * 8 + r8;
                    uint32_t g = ks * 2 + (q >> 1);
                    uint32_t ad = tb + pa * 8192 + (row << 6) +
                                  (((g + (row >> 1)) & 3) << 4);
                    LDSM4(a[mb][0], a[mb][1], a[mb][2], a[mb][3], ad);
                }
#pragma unroll
                for (int pb = 0; pb < 3 - pa; ++pb)
#pragma unroll
                    for (int mb = 0; mb < 4; ++mb)
#pragma unroll
                        for (int nb = 0; nb < 4; ++nb)
                            MMA16816(acc[mb][nb], a[mb], bfr[pb][nb][0],
                                     bfr[pb][nb][1]);
            }
        }
    }

    // ---- Epilogue: BN + ReLU from fragments, float2 stores (padded out) ----
    const int colb = t0 + wn * 32 + (lane & 3) * 2;
#pragma unroll
    for (int mb = 0; mb < 4; ++mb) {
        const int row0 = wm * 64 + mb * 16 + (lane >> 2);
        const float i0 = sInv[row0], b0 = sBb[row0];
        const float i1 = sInv[row0 + 8], b1 = sBb[row0 + 8];
        float* o0 = out + ((size_t)b * 768 + co0 + row0) * TSo + colb;
        float* o1 = o0 + (size_t)8 * TSo;
#pragma unroll
        for (int nb = 0; nb < 4; ++nb) {
            float2 v0, v1;
            v0.x = fmaxf(acc[mb][nb][0] * i0 + b0, 0.0f);
            v0.y = fmaxf(acc[mb][nb][1] * i0 + b0, 0.0f);
            v1.x = fmaxf(acc[mb][nb][2] * i1 + b1, 0.0f);
            v1.y = fmaxf(acc[mb][nb][3] * i1 + b1, 0.0f);
            *(float2*)(o0 + nb * 8) = v0;
            *(float2*)(o1 + nb * 8) = v1;
        }
    }
}

// ---------------------------------------------------------------------------
// 1x1 conv (w6) + bias + transpose to [B][T'][D]
// ---------------------------------------------------------------------------
__global__ void transpose_w6_kernel(const float* __restrict__ w6,
                                    float* __restrict__ w6t) {
    int idx = blockIdx.x * 256 + threadIdx.x;
    if (idx >= 768 * 64) return;
    int d = idx & 63;
    int ci = idx >> 6;
    w6t[idx] = w6[(size_t)d * 768 + ci];
}

__global__ void conv6_kernel(const float* __restrict__ x,
                             const float* __restrict__ w6t,
                             const float* __restrict__ b6,
                             float* __restrict__ z) {
    __shared__ float xsm[8][768];
    __shared__ float ws[64][64];
    const int b = blockIdx.y;
    const int t0 = blockIdx.x * 8;
    const int tid = threadIdx.x;

    for (int idx = tid; idx < 8 * 768; idx += 512) {
        int ci = idx >> 3, tl = idx & 7;
        int t = t0 + tl;
        xsm[tl][ci] = (t < 511) ? x[((size_t)b * 768 + ci) * 512 + t] : 0.0f;
    }
    const int tl = tid >> 6;
    const int d = tid & 63;
    float acc = 0.0f;
    for (int c0 = 0; c0 < 768; c0 += 64) {
        __syncthreads();
        for (int idx = tid; idx < 64 * 64; idx += 512) {
            int cc = idx >> 6, dd = idx & 63;
            ws[cc][dd] = w6t[(size_t)(c0 + cc) * 64 + dd];
        }
        __syncthreads();
#pragma unroll
        for (int cc = 0; cc < 64; ++cc) acc = fmaf(xsm[tl][c0 + cc], ws[cc][d], acc);
    }
    int t = t0 + tl;
    if (t < 511) z[((size_t)b * 511 + t) * 64 + d] = acc + b6[d];
}

// ---------------------------------------------------------------------------
// VQ (unchanged, passing)
// ---------------------------------------------------------------------------
__global__ void vq_init_kernel(const float* __restrict__ emb,
                               float* __restrict__ enorm,
                               float* __restrict__ counts,
                               float* __restrict__ loss) {
    int c = threadIdx.x;
    float s = 0.0f;
#pragma unroll
    for (int dd = 0; dd < 64; ++dd) {
        float e = emb[(size_t)c * 64 + dd];
        s = fmaf(e, e, s);
    }
    enorm[c] = s;
    counts[c] = 0.0f;
    if (c == 0) loss[0] = 0.0f;
}

__global__ void vq_kernel(const float* __restrict__ z,
                          const float* __restrict__ emb,
                          const float* __restrict__ enorm,
                          float* __restrict__ out,
                          float* __restrict__ loss,
                          float* __restrict__ counts) {
    __shared__ float sE[128 * 64];
    __shared__ float sN[128];
    __shared__ float red[128];
    const int tid = threadIdx.x;
    const int row = blockIdx.x * 128 + tid;
    const bool valid = row < 16352;

    float zr[64];
    if (valid) {
#pragma unroll
        for (int k = 0; k < 16; ++k)
            *(float4*)&zr[k * 4] = *(const float4*)&z[(size_t)row * 64 + k * 4];
    } else {
#pragma unroll
        for (int k = 0; k < 64; ++k) zr[k] = 0.0f;
    }

    float best = 3.4e38f;
    int bi = 0;
    for (int c0 = 0; c0 < 512; c0 += 128) {
        __syncthreads();
        for (int k = tid; k < 2048; k += 128)
            ((float4*)sE)[k] = ((const float4*)(emb + (size_t)c0 * 64))[k];
        sN[tid] = enorm[c0 + tid];
        __syncthreads();
        for (int c = 0; c < 128; ++c) {
            const float* e = &sE[c * 64];
            float dot = 0.0f;
#pragma unroll
            for (int dd = 0; dd < 64; ++dd) dot = fmaf(zr[dd], e[dd], dot);
            float dist = fmaf(-2.0f, dot, sN[c]);
            if (dist < best) { best = dist; bi = c0 + c; }
        }
    }

    float diff2 = 0.0f;
    if (valid) {
        const float* e = emb + (size_t)bi * 64;
#pragma unroll
        for (int dd = 0; dd < 64; ++dd) {
            float ev = e[dd];
            out[(size_t)row * 64 + dd] = ev;
            float df = zr[dd] - ev;
            diff2 = fmaf(df, df, diff2);
        }
        atomicAdd(&counts[bi], 1.0f);
    }
    red[tid] = diff2;
    __syncthreads();
    for (int s = 64; s > 0; s >>= 1) {
        if (tid < s) red[tid] += red[tid + s];
        __syncthreads();
    }
    if (tid == 0) atomicAdd(loss, red[0]);
}

__global__ void vq_final_kernel(const float* __restrict__ counts,
                                const float* __restrict__ loss,
                                float* __restrict__ out) {
    __shared__ float red[512];
    int tid = threadIdx.x;
    float avg = counts[tid] * (1.0f / 16352.0f);
    red[tid] = avg * logf(avg + 1e-10f);
    __syncthreads();
    for (int s = 256; s > 0; s >>= 1) {
        if (tid < s) red[tid] += red[tid + s];
        __syncthreads();
    }
    if (tid == 0) {
        out[1046528] = 0.25f * loss[0] * (1.0f / 1046528.0f);
        out[1046529] = expf(-red[0]);
    }
}

// ---------------------------------------------------------------------------
// kernel_launch
// ---------------------------------------------------------------------------
extern "C" void kernel_launch(void* const* d_in, const int* in_sizes, int n_in,
                              void* d_out, int out_size) {
    const float* mels = (const float*)d_in[0];
    const float* w1 = (const float*)d_in[1];
    const float* w2 = (const float*)d_in[2];
    const float* w3 = (const float*)d_in[3];
    const float* w4 = (const float*)d_in[4];
    const float* w5 = (const float*)d_in[5];
    const float* w6 = (const float*)d_in[6];
    const float* b6 = (const float*)d_in[7];
    const float* bng = (const float*)d_in[8];
    const float* bnb = (const float*)d_in[9];
    const float* bnm = (const float*)d_in[10];
    const float* bnv = (const float*)d_in[11];
    const float* emb = (const float*)d_in[12];
    float* out = (float*)d_out;

    float *bufA, *bufB, *w6t, *z, *enorm, *counts, *loss;
    __nv_bfloat16 *wsp, *xsbuf;
    cudaGetSymbolAddress((void**)&bufA, g_bufA);
    cudaGetSymbolAddress((void**)&bufB, g_bufB);
    cudaGetSymbolAddress((void**)&wsp, g_wsplit);
    cudaGetSymbolAddress((void**)&xsbuf, g_xs);
    cudaGetSymbolAddress((void**)&w6t, g_w6t);
    cudaGetSymbolAddress((void**)&z, g_z);
    cudaGetSymbolAddress((void**)&enorm, g_enorm);
    cudaGetSymbolAddress((void**)&counts, g_counts);
    cudaGetSymbolAddress((void**)&loss, g_loss);

    const int SMEM = 1024 + 2 * 6 * 8192;  // 99328
    cudaFuncSetAttribute(conv_mma_kernel<80, 3>,
                         cudaFuncAttributeMaxDynamicSharedMemorySize, SMEM);
    cudaFuncSetAttribute(conv_mma_kernel<768, 3>,
                         cudaFuncAttributeMaxDynamicSharedMemorySize, SMEM);
    cudaFuncSetAttribute(conv_mma_kernel<768, 4>,
                         cudaFuncAttributeMaxDynamicSharedMemorySize, SMEM);

    auto xsplit = [&](const float* x, int CIN, int T_in, int TS_in, int TSo,
                      int S, int PAD, int KS) {
        int total = KS * 32 * CIN * (TSo / 2);
        xsplit_kernel<<<(total + 255) / 256, 256>>>(x, xsbuf, CIN, T_in, TS_in,
                                                    TSo, S, PAD, KS, total);
    };

    // Layer 1: [32,80,1024] -> [32,768,1022] (pad 1024)
    split_w_kernel<<<(768 * 256 + 255) / 256, 256>>>(w1, wsp, 80, 3, 256);
    xsplit(mels, 80, 1024, 1024, 1024, 1, 0, 3);
    conv_mma_kernel<80, 3><<<dim3(8, 6, 32), 256, SMEM>>>(
        xsbuf, wsp, bng + 0, bnb + 0, bnm + 0, bnv + 0, bufA, 1024, 1022);

    // Layer 2
    split_w_kernel<<<(768 * 2304 + 255) / 256, 256>>>(w2, wsp, 768, 3, 2304);
    xsplit(bufA, 768, 1022, 1024, 1024, 1, 1, 3);
    conv_mma_kernel<768, 3><<<dim3(8, 6, 32), 256, SMEM>>>(
        xsbuf, wsp, bng + 768, bnb + 768, bnm + 768, bnv + 768, bufB, 1024, 1022);

    // Layer 3 (stride 2) -> T=511 (pad 512)
    split_w_kernel<<<(768 * 3072 + 255) / 256, 256>>>(w3, wsp, 768, 4, 3072);
    xsplit(bufB, 768, 1022, 1024, 512, 2, 1, 4);
    conv_mma_kernel<768, 4><<<dim3(4, 6, 32), 256, SMEM>>>(
        xsbuf, wsp, bng + 1536, bnb + 1536, bnm + 1536, bnv + 1536, bufA, 512, 511);

    // Layer 4
    split_w_kernel<<<(768 * 2304 + 255) / 256, 256>>>(w4, wsp, 768, 3, 2304);
    xsplit(bufA, 768, 511, 512, 512, 1, 1, 3);
    conv_mma_kernel<768, 3><<<dim3(4, 6, 32), 256, SMEM>>>(
        xsbuf, wsp, bng + 2304, bnb + 2304, bnm + 2304, bnv + 2304, bufB, 512, 511);

    // Layer 5
    split_w_kernel<<<(768 * 2304 + 255) / 256, 256>>>(w5, wsp, 768, 3, 2304);
    xsplit(bufB, 768, 511, 512, 512, 1, 1, 3);
    conv_mma_kernel<768, 3><<<dim3(4, 6, 32), 256, SMEM>>>(
        xsbuf, wsp, bng + 3072, bnb + 3072, bnm + 3072, bnv + 3072, bufA, 512, 511);

    // 1x1 conv + transpose -> z [32,511,64]
    transpose_w6_kernel<<<(768 * 64 + 255) / 256, 256>>>(w6, w6t);
    conv6_kernel<<<dim3(64, 32), 512>>>(bufA, w6t, b6, z);

    // VQ
    vq_init_kernel<<<1, 512>>>(emb, enorm, counts, loss);
    vq_kernel<<<128, 128>>>(z, emb, enorm, out, loss, counts);
    vq_final_kernel<<<1, 512>>>(counts, loss, out);
}